// round 16
// baseline (speedup 1.0000x reference)
#include <cuda_runtime.h>
#include <cuda_fp16.h>
#include <math.h>
#include <stdint.h>

// ---------------------------------------------------------------- constants
#define BSZ 4096
#define U   1024
#define FOURU 4096
#define M   20
#define OUT_ROW 1086
#define NS_ROW  1026
#define OUT_NS_OFF (BSZ * OUT_ROW)
#define STATES_ROW 1026

// stage GEMM tiling (R7 config: 512 threads, 16 warps 4x4, warp tile 32x32)
// Change vs R7: NSTG 4 -> 5, prefetch depth 3 -> 4. Nothing else.
#define BM 128
#define BN 128
#define BK 32
#define NK (U / BK)                    // 32 k-iterations
#define NTHREADS 512
#define ROWH 40                        // smem row stride in halves (32 + 8 pad)
#define ARR_BYTES (BM * ROWH * 2)      // 10240 B per tile array
#define STG_BYTES (2 * ARR_BYTES)      // A, B
#define NSTG 5
#define EPI_OFF (NSTG * STG_BYTES)     // 102400
#define SMEM_BYTES (EPI_OFF + 6 * 512) // 105472 (x2 CTAs = 211KB < 228KB)

// ---------------------------------------------------------------- scratch
__device__ __half g_Bh[4096u * 1024u];   // R^T fp16, [n, k]
__device__ __half g_A1[BSZ * U];         // h fp16
__device__ __half g_A2[BSZ * U];         // r*h fp16
__device__ __half g_A3[BSZ * U];         // h_new fp16
__device__ float g_z[BSZ * U];
__device__ float g_gmm[BSZ * 64];

// ---------------------------------------------------------------- utils
__device__ __forceinline__ uint32_t smem_u32(const void* p) {
    uint32_t a;
    asm("{ .reg .u64 t; cvta.to.shared.u64 t, %1; cvt.u32.u64 %0, t; }"
        : "=r"(a) : "l"(p));
    return a;
}
#define CP_ASYNC16(dst, src) \
    asm volatile("cp.async.cg.shared.global [%0], [%1], 16;" :: "r"(dst), "l"(src))
#define CP_COMMIT() asm volatile("cp.async.commit_group;")
#define CP_WAIT(n)  asm volatile("cp.async.wait_group %0;" :: "n"(n))
#define LDSM_X4(r0, r1, r2, r3, addr) \
    asm volatile("ldmatrix.sync.aligned.m8n8.x4.shared.b16 {%0,%1,%2,%3}, [%4];" \
        : "=r"(r0), "=r"(r1), "=r"(r2), "=r"(r3) : "r"(addr))

__device__ __forceinline__ void mma16816(float* c, const uint32_t* a, const uint32_t* b) {
    asm volatile(
        "mma.sync.aligned.m16n8k16.row.col.f32.f16.f16.f32 "
        "{%0,%1,%2,%3}, {%4,%5,%6,%7}, {%8,%9}, {%0,%1,%2,%3};"
        : "+f"(c[0]), "+f"(c[1]), "+f"(c[2]), "+f"(c[3])
        : "r"(a[0]), "r"(a[1]), "r"(a[2]), "r"(a[3]), "r"(b[0]), "r"(b[1]));
}

// ---------------------------------------------------------------- prep kernels
__global__ void zero_gmm_kernel() {
    g_gmm[blockIdx.x * 1024 + threadIdx.x] = 0.0f;
}

// Transpose R: [k,4096] fp32 -> g_Bh[n,1024] fp16
__global__ void prep_B_kernel(const float* __restrict__ R) {
    __shared__ float t[32][33];
    const int n0 = blockIdx.x * 32, k0 = blockIdx.y * 32;
    const int tx = threadIdx.x, ty = threadIdx.y;
    #pragma unroll
    for (int i = 0; i < 4; i++)
        t[ty + i * 8][tx] = R[(size_t)(k0 + ty + i * 8) * FOURU + n0 + tx];
    __syncthreads();
    #pragma unroll
    for (int i = 0; i < 4; i++) {
        const int n = n0 + ty + i * 8, k = k0 + tx;
        g_Bh[(size_t)n * U + k] = __float2half(t[tx][ty + i * 8]);
    }
}

// Convert h (states[:, :U]) to fp16
__global__ void prep_A1_kernel(const float* __restrict__ states) {
    const int idx = blockIdx.x * 256 + threadIdx.x;
    const int b = idx >> 10, k = idx & 1023;
    g_A1[idx] = __float2half(states[(size_t)b * STATES_ROW + k]);
}

// ---------------------------------------------------------------- stage GEMM
// MODE 1: zr = h@R[:,0:2048]  (z for bx<8, r for bx>=8)
// MODE 2: hh = (r*h)@R[:,2048:3072] -> GRU blend, write h/new_state
// MODE 3: o  = h@R[:,3072:4096]     -> tanh, write out
// 512 threads, 16 warps in 4x4 grid, 32x32 warp tile.
template<int MODE>
__global__ __launch_bounds__(NTHREADS, 2)
void stage_mma(const float* __restrict__ states,
               const int*   __restrict__ inp,
               const float* __restrict__ kernel_c,
               const float* __restrict__ bias_z,
               const float* __restrict__ bias,
               const float* __restrict__ kernel_d,
               float* __restrict__ out)
{
    extern __shared__ char smem[];
    const uint32_t sb = smem_u32(smem);

    const int tid  = threadIdx.x;
    const int wid  = tid >> 5;
    const int lane = tid & 31;
    const int wM   = wid >> 2;          // 0..3
    const int wN   = wid & 3;           // 0..3
    const int g    = lane >> 2;         // 0..7
    const int tig  = lane & 3;          // 0..3

    const int rowBase  = blockIdx.y * BM;
    const int bx       = blockIdx.x;
    const int stageOff = (MODE == 1) ? 0 : (MODE == 2 ? 2048 : 3072);
    const int nAbs     = stageOff + bx * BN;       // col base in 4096 pre-space

    const __half* Ah = (MODE == 1) ? g_A1 : (MODE == 2 ? g_A2 : g_A3);

    // epilogue smem
    int*   ch_s   = (int*)  (smem + EPI_OFF);
    float* d0_s   = (float*)(smem + EPI_OFF + 512);
    float* d1_s   = (float*)(smem + EPI_OFF + 1024);
    float* kd0_s  = (float*)(smem + EPI_OFF + 1536);
    float* kd1_s  = (float*)(smem + EPI_OFF + 2048);
    float* bias_s = (float*)(smem + EPI_OFF + 2560);
    if (tid < BM) {
        const int i = tid;
        const int b = rowBase + i;
        ch_s[i] = inp[b];
        d0_s[i] = states[(size_t)b * STATES_ROW + U];
        d1_s[i] = states[(size_t)b * STATES_ROW + U + 1];
        kd0_s[i] = kernel_d[nAbs + i];
        kd1_s[i] = kernel_d[FOURU + nAbs + i];
        const int nsc = bx * BN + i;    // stage-local col
        float bv;
        if (MODE == 1) bv = (nsc < U) ? bias_z[nsc] : bias[nsc - U];
        else if (MODE == 2) bv = bias[U + nsc];
        else bv = bias[2 * U + nsc];
        bias_s[i] = bv;
    }

    // issue cp.async for one pipeline slot (A + B, 1 chunk each per thread)
    auto issue = [&](int slot, int k0) {
        const uint32_t bbase = sb + slot * STG_BYTES;
        const int r = tid >> 2, c = tid & 3;
        const uint32_t d = r * 80 + c * 16;
        const size_t asrc = (size_t)(rowBase + r) * U + k0 + c * 8;
        const size_t bsrc = (size_t)(nAbs + r) * U + k0 + c * 8;
        CP_ASYNC16(bbase + d,             (const void*)(Ah + asrc));
        CP_ASYNC16(bbase + ARR_BYTES + d, (const void*)(g_Bh + bsrc));
        CP_COMMIT();
    };

    float acc[2][4][4];
    #pragma unroll
    for (int i = 0; i < 2; i++)
        #pragma unroll
        for (int j = 0; j < 4; j++)
            #pragma unroll
            for (int q = 0; q < 4; q++) acc[i][j][q] = 0.0f;

    issue(0, 0);
    issue(1, BK);
    issue(2, 2 * BK);
    issue(3, 3 * BK);

    for (int kb = 0; kb < NK; kb++) {
        if (kb <= NK - 4)      { CP_WAIT(3); }
        else if (kb == NK - 3) { CP_WAIT(2); }
        else if (kb == NK - 2) { CP_WAIT(1); }
        else                   { CP_WAIT(0); }
        __syncthreads();
        if (kb + 4 < NK) issue((kb + 4) % NSTG, (kb + 4) * BK);

        const uint32_t bufA = sb + (kb % NSTG) * STG_BYTES;
        const uint32_t bufB = bufA + ARR_BYTES;

        #pragma unroll
        for (int s16 = 0; s16 < 2; s16++) {
            // B fragments: 2x ldmatrix.x4 covers 4 n-blocks of 8
            uint32_t bh[4][2];
            #pragma unroll
            for (int p = 0; p < 2; p++) {
                const int n  = wN * 32 + p * 16 + ((lane >> 4) << 3) + (lane & 7);
                const int kk = s16 * 16 + ((lane >> 3) & 1) * 8;
                LDSM_X4(bh[2 * p][0], bh[2 * p][1], bh[2 * p + 1][0], bh[2 * p + 1][1],
                        bufB + (n * ROWH + kk) * 2);
            }
            #pragma unroll
            for (int mf = 0; mf < 2; mf++) {
                const int row = wM * 32 + mf * 16 + (lane & 15);
                const int kk  = s16 * 16 + (lane >> 4) * 8;
                uint32_t ah[4];
                LDSM_X4(ah[0], ah[1], ah[2], ah[3], bufA + (row * ROWH + kk) * 2);
                #pragma unroll
                for (int nf = 0; nf < 4; nf++)
                    mma16816(acc[mf][nf], ah, bh[nf]);
            }
        }
    }

    // ---------------- fused epilogue
    const bool zHalf = (MODE == 1) && (bx < 8);
    #pragma unroll
    for (int mf = 0; mf < 2; mf++) {
        #pragma unroll
        for (int hh = 0; hh < 2; hh++) {
            const int row = wM * 32 + mf * 16 + g + hh * 8;
            const int b   = rowBase + row;
            const int ch  = ch_s[row];
            const float d0 = d0_s[row], d1 = d1_s[row];
            #pragma unroll
            for (int nf = 0; nf < 4; nf++) {
                const int col = wN * 32 + nf * 8 + tig * 2;   // local col (even)
                const float2 kc = *(const float2*)(kernel_c + (size_t)ch * FOURU + nAbs + col);
                float v0 = acc[mf][nf][hh * 2]     + kc.x + d0 * kd0_s[col]     + d1 * kd1_s[col]     + bias_s[col];
                float v1 = acc[mf][nf][hh * 2 + 1] + kc.y + d0 * kd0_s[col + 1] + d1 * kd1_s[col + 1] + bias_s[col + 1];
                if (MODE == 1) {
                    const float s0 = 1.0f / (1.0f + expf(-v0));
                    const float s1 = 1.0f / (1.0f + expf(-v1));
                    if (zHalf) {
                        const int n = bx * BN + col;
                        *(float2*)&g_z[(size_t)b * U + n] = make_float2(s0, s1);
                    } else {
                        const int n2 = (bx - 8) * BN + col;
                        const float2 hv = *(const float2*)(states + (size_t)b * STATES_ROW + n2);
                        *(__half2*)&g_A2[(size_t)b * U + n2] =
                            __halves2half2(__float2half(s0 * hv.x), __float2half(s1 * hv.y));
                    }
                } else if (MODE == 2) {
                    const int n = bx * BN + col;
                    const float2 z2  = *(const float2*)&g_z[(size_t)b * U + n];
                    const float2 ho2 = *(const float2*)(states + (size_t)b * STATES_ROW + n);
                    const float hn0 = z2.x * ho2.x + (1.0f - z2.x) * tanhf(v0);
                    const float hn1 = z2.y * ho2.y + (1.0f - z2.y) * tanhf(v1);
                    *(float2*)&out[OUT_NS_OFF + (size_t)b * NS_ROW + n] = make_float2(hn0, hn1);
                    *(__half2*)&g_A3[(size_t)b * U + n] =
                        __halves2half2(__float2half(hn0), __float2half(hn1));
                } else {
                    const int n = bx * BN + col;
                    *(float2*)&out[(size_t)b * OUT_ROW + n] = make_float2(tanhf(v0), tanhf(v1));
                }
            }
        }
    }
}

// ---------------------------------------------------------------- GMM head
// R7 exact: scalar A loads (alignment-safe for OUT_ROW=1086), atomicAdd accumulate.
__global__ __launch_bounds__(256)
void gmm_partial(const float* __restrict__ o_src,   // == out (o in first U cols)
                 const float* __restrict__ W)       // (1024, 60)
{
    __shared__ float As[16][68];
    __shared__ float Ws[16][64];
    const int tid = threadIdx.x;
    const int tx = tid & 15, ty = tid >> 4;
    const int rowBase = blockIdx.x * 64;
    const int kBase   = blockIdx.y * 128;

    float acc[4][4];
    #pragma unroll
    for (int i = 0; i < 4; i++)
        #pragma unroll
        for (int j = 0; j < 4; j++) acc[i][j] = 0.0f;

    for (int k0 = kBase; k0 < kBase + 128; k0 += 16) {
        #pragma unroll
        for (int i = 0; i < 4; i++) {
            const int idx = tid + i * 256;
            const int kk = idx & 15, r = idx >> 4;
            As[kk][r] = o_src[(size_t)(rowBase + r) * OUT_ROW + k0 + kk];
        }
        #pragma unroll
        for (int i = 0; i < 4; i++) {
            const int idx = tid + i * 256;
            const int c = idx & 63, kk = idx >> 6;
            Ws[kk][c] = (c < 60) ? W[(size_t)(k0 + kk) * 60 + c] : 0.0f;
        }
        __syncthreads();
        #pragma unroll
        for (int kk = 0; kk < 16; kk++) {
            float a[4], bv[4];
            #pragma unroll
            for (int i = 0; i < 4; i++) a[i] = As[kk][ty * 4 + i];
            const float4 w4 = *(const float4*)(&Ws[kk][tx * 4]);
            bv[0] = w4.x; bv[1] = w4.y; bv[2] = w4.z; bv[3] = w4.w;
            #pragma unroll
            for (int i = 0; i < 4; i++)
                #pragma unroll
                for (int j = 0; j < 4; j++)
                    acc[i][j] = fmaf(a[i], bv[j], acc[i][j]);
        }
        __syncthreads();
    }
    #pragma unroll
    for (int i = 0; i < 4; i++)
        #pragma unroll
        for (int j = 0; j < 4; j++)
            atomicAdd(&g_gmm[(size_t)(rowBase + ty * 4 + i) * 64 + tx * 4 + j], acc[i][j]);
}

__global__ __launch_bounds__(128)
void gmm_finish(const float* __restrict__ bg, float* __restrict__ out) {
    const int b = blockIdx.x * 128 + threadIdx.x;
    float gv[60];
    #pragma unroll
    for (int j = 0; j < 60; j++) gv[j] = g_gmm[(size_t)b * 64 + j] + bg[j];
    float e[M], s = 0.0f;
    #pragma unroll
    for (int j = 0; j < M; j++) {
        float ev = expf(gv[j]);
        ev = fminf(fmaxf(ev, 1e-10f), 1e10f);
        e[j] = ev; s += ev;
    }
    const float inv = 1.0f / s;
    float xp = 0.0f, yp = 0.0f;
    const size_t base = (size_t)b * OUT_ROW + U;
    #pragma unroll
    for (int j = 0; j < M; j++) {
        const float pi = e[j] * inv;
        out[base + j]         = pi;
        out[base + M + j]     = gv[M + j];
        out[base + 2 * M + j] = gv[2 * M + j];
        xp = fmaf(pi, gv[M + j], xp);
        yp = fmaf(pi, gv[2 * M + j], yp);
    }
    out[base + 3 * M]     = xp;
    out[base + 3 * M + 1] = yp;
    out[OUT_NS_OFF + (size_t)b * NS_ROW + U]     = xp;
    out[OUT_NS_OFF + (size_t)b * NS_ROW + U + 1] = yp;
}

// ---------------------------------------------------------------- launch
extern "C" void kernel_launch(void* const* d_in, const int* in_sizes, int n_in,
                              void* d_out, int out_size)
{
    const int*   inp      = (const int*)  d_in[0];
    const float* states   = (const float*)d_in[1];
    const float* bias_z   = (const float*)d_in[2];
    const float* R        = (const float*)d_in[3];
    const float* kernel_c = (const float*)d_in[4];
    const float* bias     = (const float*)d_in[5];
    const float* kernel_d = (const float*)d_in[6];
    const float* Wgmm     = (const float*)d_in[7];
    const float* bgmm     = (const float*)d_in[8];
    float* out = (float*)d_out;

    cudaFuncSetAttribute(stage_mma<1>, cudaFuncAttributeMaxDynamicSharedMemorySize, SMEM_BYTES);
    cudaFuncSetAttribute(stage_mma<2>, cudaFuncAttributeMaxDynamicSharedMemorySize, SMEM_BYTES);
    cudaFuncSetAttribute(stage_mma<3>, cudaFuncAttributeMaxDynamicSharedMemorySize, SMEM_BYTES);

    zero_gmm_kernel<<<256, 1024>>>();
    prep_B_kernel<<<dim3(128, 32), dim3(32, 8)>>>(R);
    prep_A1_kernel<<<BSZ * U / 256, 256>>>(states);

    dim3 blk(NTHREADS);
    stage_mma<1><<<dim3(16, BSZ / BM), blk, SMEM_BYTES>>>(
        states, inp, kernel_c, bias_z, bias, kernel_d, out);
    stage_mma<2><<<dim3(8, BSZ / BM), blk, SMEM_BYTES>>>(
        states, inp, kernel_c, bias_z, bias, kernel_d, out);
    stage_mma<3><<<dim3(8, BSZ / BM), blk, SMEM_BYTES>>>(
        states, inp, kernel_c, bias_z, bias, kernel_d, out);

    gmm_partial<<<dim3(BSZ / 64, 8), dim3(256)>>>(out, Wgmm);
    gmm_finish<<<BSZ / 128, 128>>>(bgmm, out);
}

// round 17
// speedup vs baseline: 1.1360x; 1.1360x over previous
#include <cuda_runtime.h>
#include <cuda_fp16.h>
#include <math.h>
#include <stdint.h>

// ---------------------------------------------------------------- constants
#define BSZ 4096
#define U   1024
#define FOURU 4096
#define M   20
#define OUT_ROW 1086
#define NS_ROW  1026
#define OUT_NS_OFF (BSZ * OUT_ROW)
#define STATES_ROW 1026

// stage GEMM tiling (R7 config: 512 threads, 16 warps 4x4, warp tile 32x32)
#define BM 128
#define BN 128
#define BK 32
#define NK (U / BK)                    // 32 k-iterations
#define NTHREADS 512
#define ROWH 40                        // smem row stride in halves (32 + 8 pad)
#define ARR_BYTES (BM * ROWH * 2)      // 10240 B per tile array
#define STG_BYTES (2 * ARR_BYTES)      // A, B
#define NSTG 4
#define EPI_OFF (NSTG * STG_BYTES)     // 81920
#define SMEM_BYTES (EPI_OFF + 6 * 512)

// ---------------------------------------------------------------- scratch
__device__ __half g_Bh[4096u * 1024u];   // R^T fp16, [n, k]
__device__ __half g_A1[BSZ * U];         // h fp16
__device__ __half g_A2[BSZ * U];         // r*h fp16
__device__ __half g_A3[BSZ * U];         // h_new fp16
__device__ __half g_z[BSZ * U];          // z fp16 (was fp32)
__device__ float g_gmm[BSZ * 64];

// ---------------------------------------------------------------- utils
__device__ __forceinline__ uint32_t smem_u32(const void* p) {
    uint32_t a;
    asm("{ .reg .u64 t; cvta.to.shared.u64 t, %1; cvt.u32.u64 %0, t; }"
        : "=r"(a) : "l"(p));
    return a;
}
#define CP_ASYNC16(dst, src) \
    asm volatile("cp.async.cg.shared.global [%0], [%1], 16;" :: "r"(dst), "l"(src))
#define CP_COMMIT() asm volatile("cp.async.commit_group;")
#define CP_WAIT(n)  asm volatile("cp.async.wait_group %0;" :: "n"(n))
#define LDSM_X4(r0, r1, r2, r3, addr) \
    asm volatile("ldmatrix.sync.aligned.m8n8.x4.shared.b16 {%0,%1,%2,%3}, [%4];" \
        : "=r"(r0), "=r"(r1), "=r"(r2), "=r"(r3) : "r"(addr))

__device__ __forceinline__ void mma16816(float* c, const uint32_t* a, const uint32_t* b) {
    asm volatile(
        "mma.sync.aligned.m16n8k16.row.col.f32.f16.f16.f32 "
        "{%0,%1,%2,%3}, {%4,%5,%6,%7}, {%8,%9}, {%0,%1,%2,%3};"
        : "+f"(c[0]), "+f"(c[1]), "+f"(c[2]), "+f"(c[3])
        : "r"(a[0]), "r"(a[1]), "r"(a[2]), "r"(a[3]), "r"(b[0]), "r"(b[1]));
}

// ---------------------------------------------------------------- prep kernels
__global__ void zero_gmm_kernel() {
    g_gmm[blockIdx.x * 1024 + threadIdx.x] = 0.0f;
}

// Transpose R: [k,4096] fp32 -> g_Bh[n,1024] fp16
__global__ void prep_B_kernel(const float* __restrict__ R) {
    __shared__ float t[32][33];
    const int n0 = blockIdx.x * 32, k0 = blockIdx.y * 32;
    const int tx = threadIdx.x, ty = threadIdx.y;
    #pragma unroll
    for (int i = 0; i < 4; i++)
        t[ty + i * 8][tx] = R[(size_t)(k0 + ty + i * 8) * FOURU + n0 + tx];
    __syncthreads();
    #pragma unroll
    for (int i = 0; i < 4; i++) {
        const int n = n0 + ty + i * 8, k = k0 + tx;
        g_Bh[(size_t)n * U + k] = __float2half(t[tx][ty + i * 8]);
    }
}

// Convert h (states[:, :U]) to fp16
__global__ void prep_A1_kernel(const float* __restrict__ states) {
    const int idx = blockIdx.x * 256 + threadIdx.x;
    const int b = idx >> 10, k = idx & 1023;
    g_A1[idx] = __float2half(states[(size_t)b * STATES_ROW + k]);
}

// ---------------------------------------------------------------- stage GEMM
// MODE 1: zr = h@R[:,0:2048]  (z for bx<8, r for bx>=8)
// MODE 2: hh = (r*h)@R[:,2048:3072] -> GRU blend, write h/new_state
// MODE 3: o  = h@R[:,3072:4096]     -> tanh, write out
// 512 threads, 16 warps in 4x4 grid, 32x32 warp tile.
template<int MODE>
__global__ __launch_bounds__(NTHREADS, 2)
void stage_mma(const float* __restrict__ states,
               const int*   __restrict__ inp,
               const float* __restrict__ kernel_c,
               const float* __restrict__ bias_z,
               const float* __restrict__ bias,
               const float* __restrict__ kernel_d,
               float* __restrict__ out)
{
    extern __shared__ char smem[];
    const uint32_t sb = smem_u32(smem);

    const int tid  = threadIdx.x;
    const int wid  = tid >> 5;
    const int lane = tid & 31;
    const int wM   = wid >> 2;          // 0..3
    const int wN   = wid & 3;           // 0..3
    const int g    = lane >> 2;         // 0..7
    const int tig  = lane & 3;          // 0..3

    const int rowBase  = blockIdx.y * BM;
    const int bx       = blockIdx.x;
    const int stageOff = (MODE == 1) ? 0 : (MODE == 2 ? 2048 : 3072);
    const int nAbs     = stageOff + bx * BN;       // col base in 4096 pre-space

    const __half* Ah = (MODE == 1) ? g_A1 : (MODE == 2 ? g_A2 : g_A3);

    // epilogue smem
    int*   ch_s   = (int*)  (smem + EPI_OFF);
    float* d0_s   = (float*)(smem + EPI_OFF + 512);
    float* d1_s   = (float*)(smem + EPI_OFF + 1024);
    float* kd0_s  = (float*)(smem + EPI_OFF + 1536);
    float* kd1_s  = (float*)(smem + EPI_OFF + 2048);
    float* bias_s = (float*)(smem + EPI_OFF + 2560);
    if (tid < BM) {
        const int i = tid;
        const int b = rowBase + i;
        ch_s[i] = inp[b];
        d0_s[i] = states[(size_t)b * STATES_ROW + U];
        d1_s[i] = states[(size_t)b * STATES_ROW + U + 1];
        kd0_s[i] = kernel_d[nAbs + i];
        kd1_s[i] = kernel_d[FOURU + nAbs + i];
        const int nsc = bx * BN + i;    // stage-local col
        float bv;
        if (MODE == 1) bv = (nsc < U) ? bias_z[nsc] : bias[nsc - U];
        else if (MODE == 2) bv = bias[U + nsc];
        else bv = bias[2 * U + nsc];
        bias_s[i] = bv;
    }

    // issue cp.async for one pipeline slot (A + B, 1 chunk each per thread)
    auto issue = [&](int slot, int k0) {
        const uint32_t bbase = sb + slot * STG_BYTES;
        const int r = tid >> 2, c = tid & 3;
        const uint32_t d = r * 80 + c * 16;
        const size_t asrc = (size_t)(rowBase + r) * U + k0 + c * 8;
        const size_t bsrc = (size_t)(nAbs + r) * U + k0 + c * 8;
        CP_ASYNC16(bbase + d,             (const void*)(Ah + asrc));
        CP_ASYNC16(bbase + ARR_BYTES + d, (const void*)(g_Bh + bsrc));
        CP_COMMIT();
    };

    float acc[2][4][4];
    #pragma unroll
    for (int i = 0; i < 2; i++)
        #pragma unroll
        for (int j = 0; j < 4; j++)
            #pragma unroll
            for (int q = 0; q < 4; q++) acc[i][j][q] = 0.0f;

    issue(0, 0);
    issue(1, BK);
    issue(2, 2 * BK);

    for (int kb = 0; kb < NK; kb++) {
        if (kb <= NK - 3)      { CP_WAIT(2); }
        else if (kb == NK - 2) { CP_WAIT(1); }
        else                   { CP_WAIT(0); }
        __syncthreads();
        if (kb + 3 < NK) issue((kb + 3) % NSTG, (kb + 3) * BK);

        const uint32_t bufA = sb + (kb % NSTG) * STG_BYTES;
        const uint32_t bufB = bufA + ARR_BYTES;

        #pragma unroll
        for (int s16 = 0; s16 < 2; s16++) {
            // B fragments: 2x ldmatrix.x4 covers 4 n-blocks of 8
            uint32_t bh[4][2];
            #pragma unroll
            for (int p = 0; p < 2; p++) {
                const int n  = wN * 32 + p * 16 + ((lane >> 4) << 3) + (lane & 7);
                const int kk = s16 * 16 + ((lane >> 3) & 1) * 8;
                LDSM_X4(bh[2 * p][0], bh[2 * p][1], bh[2 * p + 1][0], bh[2 * p + 1][1],
                        bufB + (n * ROWH + kk) * 2);
            }
            #pragma unroll
            for (int mf = 0; mf < 2; mf++) {
                const int row = wM * 32 + mf * 16 + (lane & 15);
                const int kk  = s16 * 16 + (lane >> 4) * 8;
                uint32_t ah[4];
                LDSM_X4(ah[0], ah[1], ah[2], ah[3], bufA + (row * ROWH + kk) * 2);
                #pragma unroll
                for (int nf = 0; nf < 4; nf++)
                    mma16816(acc[mf][nf], ah, bh[nf]);
            }
        }
    }

    // ---------------- fused epilogue
    const bool zHalf = (MODE == 1) && (bx < 8);
    #pragma unroll
    for (int mf = 0; mf < 2; mf++) {
        #pragma unroll
        for (int hh = 0; hh < 2; hh++) {
            const int row = wM * 32 + mf * 16 + g + hh * 8;
            const int b   = rowBase + row;
            const int ch  = ch_s[row];
            const float d0 = d0_s[row], d1 = d1_s[row];
            #pragma unroll
            for (int nf = 0; nf < 4; nf++) {
                const int col = wN * 32 + nf * 8 + tig * 2;   // local col (even)
                const float2 kc = *(const float2*)(kernel_c + (size_t)ch * FOURU + nAbs + col);
                float v0 = acc[mf][nf][hh * 2]     + kc.x + d0 * kd0_s[col]     + d1 * kd1_s[col]     + bias_s[col];
                float v1 = acc[mf][nf][hh * 2 + 1] + kc.y + d0 * kd0_s[col + 1] + d1 * kd1_s[col + 1] + bias_s[col + 1];
                if (MODE == 1) {
                    const float s0 = 1.0f / (1.0f + expf(-v0));
                    const float s1 = 1.0f / (1.0f + expf(-v1));
                    if (zHalf) {
                        const int n = bx * BN + col;
                        *(__half2*)&g_z[(size_t)b * U + n] =
                            __halves2half2(__float2half(s0), __float2half(s1));
                    } else {
                        const int n2 = (bx - 8) * BN + col;
                        // h_old from fp16 h (same operand the MMA consumed)
                        const float2 hv = __half22float2(*(const __half2*)&g_A1[(size_t)b * U + n2]);
                        *(__half2*)&g_A2[(size_t)b * U + n2] =
                            __halves2half2(__float2half(s0 * hv.x), __float2half(s1 * hv.y));
                    }
                } else if (MODE == 2) {
                    const int n = bx * BN + col;
                    const float2 z2  = __half22float2(*(const __half2*)&g_z[(size_t)b * U + n]);
                    const float2 ho2 = __half22float2(*(const __half2*)&g_A1[(size_t)b * U + n]);
                    const float hn0 = z2.x * ho2.x + (1.0f - z2.x) * tanhf(v0);
                    const float hn1 = z2.y * ho2.y + (1.0f - z2.y) * tanhf(v1);
                    *(float2*)&out[OUT_NS_OFF + (size_t)b * NS_ROW + n] = make_float2(hn0, hn1);
                    *(__half2*)&g_A3[(size_t)b * U + n] =
                        __halves2half2(__float2half(hn0), __float2half(hn1));
                } else {
                    const int n = bx * BN + col;
                    *(float2*)&out[(size_t)b * OUT_ROW + n] = make_float2(tanhf(v0), tanhf(v1));
                }
            }
        }
    }
}

// ---------------------------------------------------------------- GMM head
// R7 exact: scalar A loads (alignment-safe for OUT_ROW=1086), atomicAdd accumulate.
__global__ __launch_bounds__(256)
void gmm_partial(const float* __restrict__ o_src,   // == out (o in first U cols)
                 const float* __restrict__ W)       // (1024, 60)
{
    __shared__ float As[16][68];
    __shared__ float Ws[16][64];
    const int tid = threadIdx.x;
    const int tx = tid & 15, ty = tid >> 4;
    const int rowBase = blockIdx.x * 64;
    const int kBase   = blockIdx.y * 128;

    float acc[4][4];
    #pragma unroll
    for (int i = 0; i < 4; i++)
        #pragma unroll
        for (int j = 0; j < 4; j++) acc[i][j] = 0.0f;

    for (int k0 = kBase; k0 < kBase + 128; k0 += 16) {
        #pragma unroll
        for (int i = 0; i < 4; i++) {
            const int idx = tid + i * 256;
            const int kk = idx & 15, r = idx >> 4;
            As[kk][r] = o_src[(size_t)(rowBase + r) * OUT_ROW + k0 + kk];
        }
        #pragma unroll
        for (int i = 0; i < 4; i++) {
            const int idx = tid + i * 256;
            const int c = idx & 63, kk = idx >> 6;
            Ws[kk][c] = (c < 60) ? W[(size_t)(k0 + kk) * 60 + c] : 0.0f;
        }
        __syncthreads();
        #pragma unroll
        for (int kk = 0; kk < 16; kk++) {
            float a[4], bv[4];
            #pragma unroll
            for (int i = 0; i < 4; i++) a[i] = As[kk][ty * 4 + i];
            const float4 w4 = *(const float4*)(&Ws[kk][tx * 4]);
            bv[0] = w4.x; bv[1] = w4.y; bv[2] = w4.z; bv[3] = w4.w;
            #pragma unroll
            for (int i = 0; i < 4; i++)
                #pragma unroll
                for (int j = 0; j < 4; j++)
                    acc[i][j] = fmaf(a[i], bv[j], acc[i][j]);
        }
        __syncthreads();
    }
    #pragma unroll
    for (int i = 0; i < 4; i++)
        #pragma unroll
        for (int j = 0; j < 4; j++)
            atomicAdd(&g_gmm[(size_t)(rowBase + ty * 4 + i) * 64 + tx * 4 + j], acc[i][j]);
}

__global__ __launch_bounds__(128)
void gmm_finish(const float* __restrict__ bg, float* __restrict__ out) {
    const int b = blockIdx.x * 128 + threadIdx.x;
    float gv[60];
    #pragma unroll
    for (int j = 0; j < 60; j++) gv[j] = g_gmm[(size_t)b * 64 + j] + bg[j];
    float e[M], s = 0.0f;
    #pragma unroll
    for (int j = 0; j < M; j++) {
        float ev = expf(gv[j]);
        ev = fminf(fmaxf(ev, 1e-10f), 1e10f);
        e[j] = ev; s += ev;
    }
    const float inv = 1.0f / s;
    float xp = 0.0f, yp = 0.0f;
    const size_t base = (size_t)b * OUT_ROW + U;
    #pragma unroll
    for (int j = 0; j < M; j++) {
        const float pi = e[j] * inv;
        out[base + j]         = pi;
        out[base + M + j]     = gv[M + j];
        out[base + 2 * M + j] = gv[2 * M + j];
        xp = fmaf(pi, gv[M + j], xp);
        yp = fmaf(pi, gv[2 * M + j], yp);
    }
    out[base + 3 * M]     = xp;
    out[base + 3 * M + 1] = yp;
    out[OUT_NS_OFF + (size_t)b * NS_ROW + U]     = xp;
    out[OUT_NS_OFF + (size_t)b * NS_ROW + U + 1] = yp;
}

// ---------------------------------------------------------------- launch
extern "C" void kernel_launch(void* const* d_in, const int* in_sizes, int n_in,
                              void* d_out, int out_size)
{
    const int*   inp      = (const int*)  d_in[0];
    const float* states   = (const float*)d_in[1];
    const float* bias_z   = (const float*)d_in[2];
    const float* R        = (const float*)d_in[3];
    const float* kernel_c = (const float*)d_in[4];
    const float* bias     = (const float*)d_in[5];
    const float* kernel_d = (const float*)d_in[6];
    const float* Wgmm     = (const float*)d_in[7];
    const float* bgmm     = (const float*)d_in[8];
    float* out = (float*)d_out;

    cudaFuncSetAttribute(stage_mma<1>, cudaFuncAttributeMaxDynamicSharedMemorySize, SMEM_BYTES);
    cudaFuncSetAttribute(stage_mma<2>, cudaFuncAttributeMaxDynamicSharedMemorySize, SMEM_BYTES);
    cudaFuncSetAttribute(stage_mma<3>, cudaFuncAttributeMaxDynamicSharedMemorySize, SMEM_BYTES);

    zero_gmm_kernel<<<256, 1024>>>();
    prep_B_kernel<<<dim3(128, 32), dim3(32, 8)>>>(R);
    prep_A1_kernel<<<BSZ * U / 256, 256>>>(states);

    dim3 blk(NTHREADS);
    stage_mma<1><<<dim3(16, BSZ / BM), blk, SMEM_BYTES>>>(
        states, inp, kernel_c, bias_z, bias, kernel_d, out);
    stage_mma<2><<<dim3(8, BSZ / BM), blk, SMEM_BYTES>>>(
        states, inp, kernel_c, bias_z, bias, kernel_d, out);
    stage_mma<3><<<dim3(8, BSZ / BM), blk, SMEM_BYTES>>>(
        states, inp, kernel_c, bias_z, bias, kernel_d, out);

    gmm_partial<<<dim3(BSZ / 64, 8), dim3(256)>>>(out, Wgmm);
    gmm_finish<<<BSZ / 128, 128>>>(bgmm, out);
}